// round 8
// baseline (speedup 1.0000x reference)
#include <cuda_runtime.h>

// Shapes fixed by dataset: b=8, n=1024, m=2048, x_dim=1, c=3, Z=128
#define BB     8
#define NN     1024
#define MM     2048
#define MT     32          // m-rows per block
#define NCTR   12          // Hermite centers, c_l = l - 5.5, spacing 1, r = 0.5
#define KH     13          // Hermite terms k = 0..12
#define EPSV   1e-8f
#define LOG2E  1.4426950408889634f
#define K2     (-0.5f * LOG2E)   // exp(-u^2/2) = exp2(K2*u^2)

__device__ __forceinline__ float ex2f(float v) {
    float r;
    asm("ex2.approx.ftz.f32 %0, %1;" : "=f"(r) : "f"(v));
    return r;
}

// ---------------------------------------------------------------------------
// Fused kernel: 512 blocks x 384 threads (12 warps).
// Fast path:  warp w = Hermite center w.
//   Phase 1: warp scans the batch's n=1024 points, accumulates center-w moments
//            in registers, shfl-butterfly -> all lanes hold the 39 moments.
//   Phase 2: lane = m-row; Hermite series from register moments.
// Then: combine 12 centers per row, normalize, project (3->128), store.
// ---------------------------------------------------------------------------
__global__ __launch_bounds__(384)
void enc_fused(const float* __restrict__ x,
               const float* __restrict__ y,
               const float* __restrict__ t,
               const float* __restrict__ sigma,
               const float* __restrict__ W,
               const float* __restrict__ bfc,
               float* __restrict__ out)
{
    __shared__ float4 red[NCTR][MT];   // per-warp partials (6 KB)
    __shared__ float4 zfin[MT];        // (density, zn1, zn2, -)

    const int tid  = threadIdx.x;
    const int lane = tid & 31;         // m-row within tile (phase 2)
    const int wrp  = tid >> 5;         // 0..11 = center (fast) / n-slice (fallback)
    const int blk  = blockIdx.x;
    const int b    = blk >> 6;         // 64 m-tiles per batch
    const int m_base = (blk & 63) * MT;

    const float C0 = -0.5f * LOG2E * __expf(-2.f * sigma[0]);
    const float C1 = -0.5f * LOG2E * __expf(-2.f * sigma[1]);
    const float C2 = -0.5f * LOG2E * __expf(-2.f * sigma[2]);
    const float s  = __expf(sigma[0]);
    const bool fast = (C0 == C1) && (C0 == C2) && (s >= 0.8f) && (s <= 1.25f);

    float s0 = 0.f, s1 = 0.f, s2 = 0.f;

    if (fast) {
        // ---- Phase 1: moments of center `wrp` for this batch ----
        const float c     = (float)wrp - 5.5f;
        const float s_inv = 1.f / s;
        const float INVK[KH] = {0.f, 1.f, 0.5f, 1.f/3.f, 0.25f, 0.2f, 1.f/6.f,
                                1.f/7.f, 0.125f, 1.f/9.f, 0.1f, 1.f/11.f, 1.f/12.f};

        float a0[KH], a1[KH], a2[KH];
        #pragma unroll
        for (int k = 0; k < KH; ++k) { a0[k] = 0.f; a1[k] = 0.f; a2[k] = 0.f; }

        const float*  xb = x + b * NN;
        const float2* yb = reinterpret_cast<const float2*>(y + b * NN * 2);

        #pragma unroll 4
        for (int i = lane; i < NN; i += 32) {
            float xv = __ldg(xb + i) * s_inv;
            int l = (int)floorf(xv + 6.0f);
            l = min(max(l, 0), NCTR - 1);
            if (l == wrp) {
                float2 yv = __ldg(yb + i);
                float w = xv - c;
                float p = 1.f;
                a0[0] += 1.f; a1[0] += yv.x; a2[0] += yv.y;
                #pragma unroll
                for (int k = 1; k < KH; ++k) {
                    p = p * w * INVK[k];
                    a0[k] += p;
                    a1[k] = fmaf(p, yv.x, a1[k]);
                    a2[k] = fmaf(p, yv.y, a2[k]);
                }
            }
        }

        // Butterfly: afterwards every lane holds the full 39 moments
        #pragma unroll
        for (int off = 16; off; off >>= 1) {
            #pragma unroll
            for (int k = 0; k < KH; ++k) {
                a0[k] += __shfl_xor_sync(0xffffffffu, a0[k], off);
                a1[k] += __shfl_xor_sync(0xffffffffu, a1[k], off);
                a2[k] += __shfl_xor_sync(0xffffffffu, a2[k], off);
            }
        }

        // ---- Phase 2: Hermite series, lane = m-row ----
        const float tr = __ldg(t + b * MM + m_base + lane) * s_inv;
        const float u  = tr - c;
        const float E  = ex2f(K2 * u * u);

        float Hk2 = E;                    // He_0 * E
        s0 = fmaf(a0[0], Hk2, s0);
        s1 = fmaf(a1[0], Hk2, s1);
        s2 = fmaf(a2[0], Hk2, s2);
        float Hk1 = u * E;                // He_1 * E
        s0 = fmaf(a0[1], Hk1, s0);
        s1 = fmaf(a1[1], Hk1, s1);
        s2 = fmaf(a2[1], Hk1, s2);
        #pragma unroll
        for (int k = 2; k < KH; ++k) {
            float Hk = fmaf(u, Hk1, -(float)(k - 1) * Hk2);   // He recurrence * E
            s0 = fmaf(a0[k], Hk, s0);
            s1 = fmaf(a1[k], Hk, s1);
            s2 = fmaf(a2[k], Hk, s2);
            Hk2 = Hk1; Hk1 = Hk;
        }
    } else {
        // Exact direct fallback: warp wrp scans its n-slice for all 32 rows
        const float tr = __ldg(t + b * MM + m_base + lane);
        const int nstart = wrp * 86;
        const int nend   = min(NN, nstart + 86);
        const float*  xb = x + b * NN;
        const float2* yb = reinterpret_cast<const float2*>(y + b * NN * 2);
        for (int i = nstart; i < nend; ++i) {
            float  d  = tr - __ldg(xb + i);
            float2 yv = __ldg(yb + i);
            float d2 = d * d;
            float e0 = ex2f(C0 * d2);
            float e1 = ex2f(C1 * d2);
            float e2 = ex2f(C2 * d2);
            s0 += e0;
            s1 = fmaf(e1, yv.x, s1);
            s2 = fmaf(e2, yv.y, s2);
        }
    }

    red[wrp][lane] = make_float4(s0, s1, s2, 0.f);

    // W + bias into registers (column group k4 = lane)
    const int k4 = lane;
    const float4* Wv = reinterpret_cast<const float4*>(W);
    const float4 wa  = __ldg(Wv + 3 * k4);
    const float4 wb  = __ldg(Wv + 3 * k4 + 1);
    const float4 wc  = __ldg(Wv + 3 * k4 + 2);
    const float4 bbv = __ldg(reinterpret_cast<const float4*>(bfc) + k4);

    __syncthreads();

    // Combine 12 center/slice partials per row, normalize
    if (tid < MT) {
        float d0 = 0.f, d1 = 0.f, d2 = 0.f;
        #pragma unroll
        for (int wdx = 0; wdx < NCTR; ++wdx) {
            float4 p = red[wdx][tid];
            d0 += p.x; d1 += p.y; d2 += p.z;
        }
        float inv = 1.f / (d0 + EPSV);
        zfin[tid] = make_float4(d0, d1 * inv, d2 * inv, 0.f);
    }
    __syncthreads();

    // Epilogue: out[b, m_base+mi, 4*k4..4*k4+3], coalesced float4 stores
    float4* out4 = reinterpret_cast<float4*>(out);
    const size_t rowbase = (size_t)(b * MM + m_base);
    for (int mi = wrp; mi < MT; mi += NCTR) {
        float4 z = zfin[mi];      // warp-uniform broadcast LDS
        float4 o;
        o.x = fmaf(z.x, wa.x, fmaf(z.y, wa.y, fmaf(z.z, wa.z, bbv.x)));
        o.y = fmaf(z.x, wa.w, fmaf(z.y, wb.x, fmaf(z.z, wb.y, bbv.y)));
        o.z = fmaf(z.x, wb.z, fmaf(z.y, wb.w, fmaf(z.z, wc.x, bbv.z)));
        o.w = fmaf(z.x, wc.y, fmaf(z.y, wc.z, fmaf(z.z, wc.w, bbv.w)));
        out4[(rowbase + mi) * 32 + k4] = o;
    }
}

extern "C" void kernel_launch(void* const* d_in, const int* in_sizes, int n_in,
                              void* d_out, int out_size)
{
    const float* x     = (const float*)d_in[0];   // (8,1024,1)
    const float* y     = (const float*)d_in[1];   // (8,1024,2)
    const float* t     = (const float*)d_in[2];   // (8,2048,1)
    const float* sigma = (const float*)d_in[3];   // (3,)
    const float* W     = (const float*)d_in[4];   // (128,3)
    const float* bfc   = (const float*)d_in[5];   // (128,)
    float* out = (float*)d_out;                   // (8,2048,128)

    enc_fused<<<BB * (MM / MT), 384>>>(x, y, t, sigma, W, bfc, out);
}

// round 9
// speedup vs baseline: 2.1730x; 2.1730x over previous
#include <cuda_runtime.h>

// Shapes fixed by dataset: b=8, n=1024, m=2048, x_dim=1, c=3, Z=128
#define BB     8
#define NN     1024
#define MM     2048
#define MTB    64          // m-rows per block in main kernel
#define NCTR   12          // Hermite centers, c_l = l - 5.5, spacing 1, r = 0.5
#define KH     13          // Hermite terms k = 0..12
#define NMOM   (KH*3)      // 39 moments per (batch,center)
#define EPSV   1e-8f
#define LOG2E  1.4426950408889634f
#define K2     (-0.5f * LOG2E)   // exp(-u^2/2) = exp2(K2*u^2)

// Scratch: moments M[b][ctr][k][ch]
__device__ float g_moments[BB * NCTR * NMOM];

__device__ __forceinline__ float ex2f(float v) {
    float r;
    asm("ex2.approx.ftz.f32 %0, %1;" : "=f"(r) : "f"(v));
    return r;
}

// ---------------------------------------------------------------------------
// Kernel 1: moments. One block (128 thr = 4 warps) per (batch,center).
// Each warp scans a 256-point quarter (8 iters/lane), butterfly-reduces its
// 39 accumulators, then 4 warp-partials are combined through smem. No atomics.
// ---------------------------------------------------------------------------
__global__ __launch_bounds__(128)
void moments_kernel(const float* __restrict__ x,
                    const float* __restrict__ y,
                    const float* __restrict__ sigma)
{
    __shared__ float cm[4][NMOM];

    const int tid  = threadIdx.x;
    const int lane = tid & 31;
    const int wrp  = tid >> 5;
    const int b    = blockIdx.x / NCTR;
    const int ctr  = blockIdx.x % NCTR;
    const float c  = (float)ctr - 5.5f;

    const float s_inv = __expf(-sigma[0]);   // 1/scale

    const float INVK[KH] = {0.f, 1.f, 0.5f, 1.f/3.f, 0.25f, 0.2f, 1.f/6.f,
                            1.f/7.f, 0.125f, 1.f/9.f, 0.1f, 1.f/11.f, 1.f/12.f};

    float a0[KH], a1[KH], a2[KH];
    #pragma unroll
    for (int k = 0; k < KH; ++k) { a0[k] = 0.f; a1[k] = 0.f; a2[k] = 0.f; }

    const float*  xb = x + b * NN;
    const float2* yb = reinterpret_cast<const float2*>(y + b * NN * 2);

    const int ibase = wrp * (NN / 4);
    #pragma unroll
    for (int ii = 0; ii < NN / 128; ++ii) {          // 8 iters per lane
        const int i = ibase + ii * 32 + lane;
        float xv = __ldg(xb + i) * s_inv;
        int l = (int)floorf(xv + 6.0f);
        l = min(max(l, 0), NCTR - 1);
        if (l == ctr) {
            float2 yv = __ldg(yb + i);
            float w = xv - c;
            float p = 1.f;
            a0[0] += 1.f; a1[0] += yv.x; a2[0] += yv.y;
            #pragma unroll
            for (int k = 1; k < KH; ++k) {
                p = p * w * INVK[k];
                a0[k] += p;
                a1[k] = fmaf(p, yv.x, a1[k]);
                a2[k] = fmaf(p, yv.y, a2[k]);
            }
        }
    }

    // Warp butterfly (39 accumulators)
    #pragma unroll
    for (int off = 16; off; off >>= 1) {
        #pragma unroll
        for (int k = 0; k < KH; ++k) {
            a0[k] += __shfl_xor_sync(0xffffffffu, a0[k], off);
            a1[k] += __shfl_xor_sync(0xffffffffu, a1[k], off);
            a2[k] += __shfl_xor_sync(0xffffffffu, a2[k], off);
        }
    }

    if (lane == 0) {
        #pragma unroll
        for (int k = 0; k < KH; ++k) {
            cm[wrp][k * 3 + 0] = a0[k];
            cm[wrp][k * 3 + 1] = a1[k];
            cm[wrp][k * 3 + 2] = a2[k];
        }
    }
    __syncthreads();

    if (tid < NMOM)
        g_moments[(b * NCTR + ctr) * NMOM + tid] =
            cm[0][tid] + cm[1][tid] + cm[2][tid] + cm[3][tid];
}

// ---------------------------------------------------------------------------
// Kernel 2: evaluate Hermite series per m-row, normalize, project.
// 256 blocks x 384 threads. Warp = center; each warp covers 64 rows in two
// 32-lane passes. Moments + W + bias staged in smem once per block.
// ---------------------------------------------------------------------------
__global__ __launch_bounds__(384)
void main_kernel(const float* __restrict__ x,
                 const float* __restrict__ y,
                 const float* __restrict__ t,
                 const float* __restrict__ sigma,
                 const float* __restrict__ W,
                 const float* __restrict__ bfc,
                 float* __restrict__ out)
{
    __shared__ float  sM[NCTR * NMOM];   // 468 floats
    __shared__ float4 sW[96];            // W as float4 (k4-major triplets)
    __shared__ float4 sB[32];
    __shared__ float4 red[NCTR][MTB];    // 12 KB
    __shared__ float4 zfin[MTB];

    const int tid  = threadIdx.x;
    const int lane = tid & 31;
    const int wrp  = tid >> 5;          // 0..11 = center (fast) / n-slice (fallback)
    const int blk  = blockIdx.x;
    const int b    = blk >> 5;          // 32 m-tiles per batch
    const int m_base = (blk & 31) * MTB;

    const float C0 = -0.5f * LOG2E * __expf(-2.f * sigma[0]);
    const float C1 = -0.5f * LOG2E * __expf(-2.f * sigma[1]);
    const float C2 = -0.5f * LOG2E * __expf(-2.f * sigma[2]);
    const float s  = __expf(sigma[0]);
    const bool fast = (C0 == C1) && (C0 == C2) && (s >= 0.8f) && (s <= 1.25f);

    // Stage moments + W + bias in shared
    if (tid < NCTR * NMOM - 384) sM[384 + tid] = g_moments[b * (NCTR * NMOM) + 384 + tid];
    sM[tid] = g_moments[b * (NCTR * NMOM) + tid];
    if (tid < 96) sW[tid] = reinterpret_cast<const float4*>(W)[tid];
    if (tid >= 96 && tid < 128) sB[tid - 96] = reinterpret_cast<const float4*>(bfc)[tid - 96];
    __syncthreads();

    if (fast) {
        const float c     = (float)wrp - 5.5f;
        const float s_inv = 1.f / s;
        const float* Mc   = sM + wrp * NMOM;

        #pragma unroll
        for (int rg = 0; rg < 2; ++rg) {
            const int row = rg * 32 + lane;
            const float tr = __ldg(t + b * MM + m_base + row) * s_inv;
            const float u  = tr - c;
            const float E  = ex2f(K2 * u * u);

            float Hk2 = E;                    // He_0 * E
            float s0 = Mc[0] * Hk2;
            float s1 = Mc[1] * Hk2;
            float s2 = Mc[2] * Hk2;
            float Hk1 = u * E;                // He_1 * E
            s0 = fmaf(Mc[3], Hk1, s0);
            s1 = fmaf(Mc[4], Hk1, s1);
            s2 = fmaf(Mc[5], Hk1, s2);
            #pragma unroll
            for (int k = 2; k < KH; ++k) {
                float Hk = fmaf(u, Hk1, -(float)(k - 1) * Hk2);  // He recurrence * E
                s0 = fmaf(Mc[k * 3 + 0], Hk, s0);
                s1 = fmaf(Mc[k * 3 + 1], Hk, s1);
                s2 = fmaf(Mc[k * 3 + 2], Hk, s2);
                Hk2 = Hk1; Hk1 = Hk;
            }
            red[wrp][row] = make_float4(s0, s1, s2, 0.f);
        }
    } else {
        // Exact direct fallback: warp wrp scans its n-slice for all 64 rows
        const int nstart = wrp * 86;
        const int nend   = min(NN, nstart + 86);
        const float*  xb = x + b * NN;
        const float2* yb = reinterpret_cast<const float2*>(y + b * NN * 2);
        #pragma unroll
        for (int rg = 0; rg < 2; ++rg) {
            const int row = rg * 32 + lane;
            const float tr = __ldg(t + b * MM + m_base + row);
            float s0 = 0.f, s1 = 0.f, s2 = 0.f;
            for (int i = nstart; i < nend; ++i) {
                float  d  = tr - __ldg(xb + i);
                float2 yv = __ldg(yb + i);
                float d2 = d * d;
                float e0 = ex2f(C0 * d2);
                float e1 = ex2f(C1 * d2);
                float e2 = ex2f(C2 * d2);
                s0 += e0;
                s1 = fmaf(e1, yv.x, s1);
                s2 = fmaf(e2, yv.y, s2);
            }
            red[wrp][row] = make_float4(s0, s1, s2, 0.f);
        }
    }
    __syncthreads();

    // Combine 12 center/slice partials per row, normalize
    if (tid < MTB) {
        float d0 = 0.f, d1 = 0.f, d2 = 0.f;
        #pragma unroll
        for (int wdx = 0; wdx < NCTR; ++wdx) {
            float4 p = red[wdx][tid];
            d0 += p.x; d1 += p.y; d2 += p.z;
        }
        float inv = 1.f / (d0 + EPSV);
        zfin[tid] = make_float4(d0, d1 * inv, d2 * inv, 0.f);
    }
    __syncthreads();

    // Epilogue: 64 rows x 32 col-groups = 2048 float4 stores over 384 threads
    float4* out4 = reinterpret_cast<float4*>(out);
    const size_t rowbase = (size_t)(b * MM + m_base);
    for (int j = tid; j < MTB * 32; j += 384) {
        const int row = j >> 5;
        const int k4  = j & 31;
        const float4 z  = zfin[row];
        const float4 wa = sW[3 * k4];
        const float4 wb = sW[3 * k4 + 1];
        const float4 wc = sW[3 * k4 + 2];
        const float4 bb = sB[k4];
        float4 o;
        o.x = fmaf(z.x, wa.x, fmaf(z.y, wa.y, fmaf(z.z, wa.z, bb.x)));
        o.y = fmaf(z.x, wa.w, fmaf(z.y, wb.x, fmaf(z.z, wb.y, bb.y)));
        o.z = fmaf(z.x, wb.z, fmaf(z.y, wb.w, fmaf(z.z, wc.x, bb.z)));
        o.w = fmaf(z.x, wc.y, fmaf(z.y, wc.z, fmaf(z.z, wc.w, bb.w)));
        out4[(rowbase + row) * 32 + k4] = o;
    }
}

extern "C" void kernel_launch(void* const* d_in, const int* in_sizes, int n_in,
                              void* d_out, int out_size)
{
    const float* x     = (const float*)d_in[0];   // (8,1024,1)
    const float* y     = (const float*)d_in[1];   // (8,1024,2)
    const float* t     = (const float*)d_in[2];   // (8,2048,1)
    const float* sigma = (const float*)d_in[3];   // (3,)
    const float* W     = (const float*)d_in[4];   // (128,3)
    const float* bfc   = (const float*)d_in[5];   // (128,)
    float* out = (float*)d_out;                   // (8,2048,128)

    moments_kernel<<<BB * NCTR, 128>>>(x, y, sigma);
    main_kernel<<<BB * (MM / MTB), 384>>>(x, y, t, sigma, W, bfc, out);
}